// round 1
// baseline (speedup 1.0000x reference)
#include <cuda_runtime.h>
#include <cstddef>

#define T_STEPS 512
#define B_SZ 256
#define I_SZ 64
#define N_SZ 512
#define C_SZ 10
#define L_SZ 3
#define ALPHA 0.5f
#define INV_TAU 0.5f
#define SLOPE 0.01f
#define G_CTAS 128
#define NN (N_SZ * N_SZ)

// ---------------- device scratch (no allocations allowed) ----------------
__device__ float g_x[(size_t)T_STEPS * B_SZ * N_SZ];   // 256 MB: x = data@Win + b_in
__device__ float g_W[5 * NN];                          // W0,W1,W2 (diag zeroed), Wi0, Wi1
__device__ float g_bias[3 * N_SZ];                     // combined per-layer bias
__device__ float g_h[2][3][B_SZ * N_SZ];               // ping-pong states
__device__ unsigned g_cnt = 0;
__device__ unsigned g_gen = 0;

// ---------------- grid-wide barrier (all 128 CTAs resident) ----------------
__device__ __forceinline__ void gridbar() {
    __syncthreads();
    if (threadIdx.x == 0) {
        __threadfence();
        unsigned gen = *(volatile unsigned*)&g_gen;
        unsigned arrived = atomicAdd(&g_cnt, 1u);
        if (arrived == G_CTAS - 1) {
            g_cnt = 0;
            __threadfence();
            atomicExch(&g_gen, gen + 1u);
        } else {
            while (*(volatile unsigned*)&g_gen == gen) { __nanosleep(64); }
            __threadfence();
        }
    }
    __syncthreads();
}

// ---------------- prep: weights (zero diag), biases, initial state ----------------
__global__ void prep_kernel(const float* __restrict__ Whh, const float* __restrict__ bhh,
                            const float* __restrict__ Whi, const float* __restrict__ bhi,
                            const float* __restrict__ h0) {
    int idx = blockIdx.x * blockDim.x + threadIdx.x;
    if (idx < 3 * NN) {
        int rc = idx % NN;
        int r = rc / N_SZ, c = rc % N_SZ;
        g_W[idx] = (r == c) ? 0.0f : Whh[idx];
    }
    if (idx < 2 * NN) {
        g_W[3 * NN + idx] = Whi[idx];
    }
    if (idx < 3 * N_SZ) {
        int l = idx / N_SZ, c = idx % N_SZ;
        float b = bhh[idx];
        if (l >= 1) b += bhi[(l - 1) * N_SZ + c];
        g_bias[idx] = b;
    }
    if (idx < 3 * B_SZ * N_SZ) {
        int l = idx / (B_SZ * N_SZ);
        g_h[0][l][idx % (B_SZ * N_SZ)] = h0[idx];
    }
}

// ---------------- input projection: g_x = data @ Win + b_in ----------------
// M = T*B = 131072, K = 64, N = 512. Tile 64x32, micro 4x2, 256 threads.
__global__ void __launch_bounds__(256) xproj_kernel(const float* __restrict__ data,
                                                    const float* __restrict__ Win,
                                                    const float* __restrict__ bin) {
    __shared__ float Ask[64][65];   // A transposed: [k][row]
    __shared__ float Ws[64][34];    // W: [k][col]
    const int row0 = blockIdx.x * 64;
    const int col0 = blockIdx.y * 32;
    const int tid = threadIdx.x;

    // load A tile (64 rows x 64 k)
    {
        int ar = tid >> 2, ak = (tid & 3) * 4;
        #pragma unroll
        for (int it = 0; it < 4; ++it) {
            float4 v = *(const float4*)(data + (size_t)(row0 + ar) * I_SZ + ak + it * 16);
            Ask[ak + it * 16 + 0][ar] = v.x;
            Ask[ak + it * 16 + 1][ar] = v.y;
            Ask[ak + it * 16 + 2][ar] = v.z;
            Ask[ak + it * 16 + 3][ar] = v.w;
        }
    }
    // load W tile (64 k x 32 cols)
    {
        int wk = tid >> 3, wc = (tid & 7) * 4;
        #pragma unroll
        for (int it = 0; it < 2; ++it) {
            float4 v = *(const float4*)(Win + (size_t)(wk + it * 32) * N_SZ + col0 + wc);
            Ws[wk + it * 32][wc + 0] = v.x;
            Ws[wk + it * 32][wc + 1] = v.y;
            Ws[wk + it * 32][wc + 2] = v.z;
            Ws[wk + it * 32][wc + 3] = v.w;
        }
    }
    __syncthreads();

    const int tr = (tid >> 4) * 4, tc = (tid & 15) * 2;
    float acc[4][2] = {};
    #pragma unroll
    for (int k = 0; k < 64; ++k) {
        float2 w = *(const float2*)&Ws[k][tc];
        float a0 = Ask[k][tr + 0], a1 = Ask[k][tr + 1];
        float a2 = Ask[k][tr + 2], a3 = Ask[k][tr + 3];
        acc[0][0] += a0 * w.x; acc[0][1] += a0 * w.y;
        acc[1][0] += a1 * w.x; acc[1][1] += a1 * w.y;
        acc[2][0] += a2 * w.x; acc[2][1] += a2 * w.y;
        acc[3][0] += a3 * w.x; acc[3][1] += a3 * w.y;
    }
    float b0 = bin[col0 + tc], b1 = bin[col0 + tc + 1];
    #pragma unroll
    for (int i = 0; i < 4; ++i) {
        size_t base = (size_t)(row0 + tr + i) * N_SZ + col0 + tc;
        g_x[base + 0] = acc[i][0] + b0;
        g_x[base + 1] = acc[i][1] + b1;
    }
}

// ---------------- persistent recurrent kernel ----------------
// 128 CTAs x 256 threads. Output tile 32x32 (rb = bid>>4, cb = bid&15).
// Micro-tile 2x2 per thread. K streamed in 32-chunks, double-buffered SMEM.

__device__ __forceinline__ void mm_acc(const float* __restrict__ A,
                                       const float* __restrict__ W,
                                       float acc[2][2],
                                       float (*As)[32][33], float (*Ws)[32][36],
                                       int row0, int col0, int p, int q4,
                                       int tr, int tc) {
    // preload chunk 0
    {
        float4 av = *(const float4*)(A + (size_t)(row0 + p) * N_SZ + q4);
        float4 wv = *(const float4*)(W + (size_t)p * N_SZ + col0 + q4);
        As[0][q4 + 0][p] = av.x; As[0][q4 + 1][p] = av.y;
        As[0][q4 + 2][p] = av.z; As[0][q4 + 3][p] = av.w;
        *(float4*)&Ws[0][p][q4] = wv;
    }
    __syncthreads();
    #pragma unroll 1
    for (int kk = 0; kk < 16; ++kk) {
        const int buf = kk & 1;
        float4 av, wv;
        if (kk < 15) {
            int k0 = (kk + 1) * 32;
            av = *(const float4*)(A + (size_t)(row0 + p) * N_SZ + k0 + q4);
            wv = *(const float4*)(W + (size_t)(k0 + p) * N_SZ + col0 + q4);
        }
        #pragma unroll
        for (int k = 0; k < 32; ++k) {
            float a0 = As[buf][k][tr];
            float a1 = As[buf][k][tr + 1];
            float2 w = *(const float2*)&Ws[buf][k][tc];
            acc[0][0] += a0 * w.x; acc[0][1] += a0 * w.y;
            acc[1][0] += a1 * w.x; acc[1][1] += a1 * w.y;
        }
        __syncthreads();
        if (kk < 15) {
            const int nb = buf ^ 1;
            As[nb][q4 + 0][p] = av.x; As[nb][q4 + 1][p] = av.y;
            As[nb][q4 + 2][p] = av.z; As[nb][q4 + 3][p] = av.w;
            *(float4*)&Ws[nb][p][q4] = wv;
            __syncthreads();
        }
    }
}

__device__ __forceinline__ void epilogue(int layer,
                                         const float* __restrict__ hold,
                                         float* __restrict__ hnew,
                                         const float acc[2][2],
                                         const float* __restrict__ xrow,
                                         int row0, int col0, int tr, int tc) {
    #pragma unroll
    for (int i = 0; i < 2; ++i) {
        size_t base = (size_t)(row0 + tr + i) * N_SZ + col0 + tc;
        #pragma unroll
        for (int j = 0; j < 2; ++j) {
            float ho = hold[base + j];
            float xv = xrow[base + j];
            float bv = g_bias[layer * N_SZ + col0 + tc + j];
            float v = ALPHA * ho + (acc[i][j] + bv + xv) * INV_TAU;
            hnew[base + j] = (v > 0.0f) ? v : SLOPE * v;
        }
    }
}

__global__ void __launch_bounds__(256, 1) rnn_kernel() {
    __shared__ float As[2][32][33];
    __shared__ float Ws[2][32][36];
    const int bid = blockIdx.x;
    const int row0 = (bid >> 4) * 32;
    const int col0 = (bid & 15) * 32;
    const int tid = threadIdx.x;
    const int tr = (tid >> 4) * 2;
    const int tc = (tid & 15) * 2;
    const int p = tid >> 3;           // loader row / k index (0..31)
    const int q4 = (tid & 7) * 4;     // loader 4-wide offset

    for (int t = 0; t < T_STEPS; ++t) {
        const int cur = t & 1, nxt = cur ^ 1;
        const float* xrow = g_x + (size_t)t * B_SZ * N_SZ;

        // ---- stage A: n0 = f(h0, h0@W0) ----
        {
            float acc[2][2] = {};
            mm_acc(g_h[cur][0], g_W + 0 * NN, acc, As, Ws, row0, col0, p, q4, tr, tc);
            epilogue(0, g_h[cur][0], g_h[nxt][0], acc, xrow, row0, col0, tr, tc);
        }
        gridbar();
        // ---- stage B: n1 = f(h1, h1@W1 + n0@Wi0) ----
        {
            float acc[2][2] = {};
            mm_acc(g_h[cur][1], g_W + 1 * NN, acc, As, Ws, row0, col0, p, q4, tr, tc);
            mm_acc(g_h[nxt][0], g_W + 3 * NN, acc, As, Ws, row0, col0, p, q4, tr, tc);
            epilogue(1, g_h[cur][1], g_h[nxt][1], acc, xrow, row0, col0, tr, tc);
        }
        gridbar();
        // ---- stage C: n2 = f(h2, h2@W2 + n1@Wi1) ----
        {
            float acc[2][2] = {};
            mm_acc(g_h[cur][2], g_W + 2 * NN, acc, As, Ws, row0, col0, p, q4, tr, tc);
            mm_acc(g_h[nxt][1], g_W + 4 * NN, acc, As, Ws, row0, col0, p, q4, tr, tc);
            epilogue(2, g_h[cur][2], g_h[nxt][2], acc, xrow, row0, col0, tr, tc);
        }
        gridbar();
    }
}

// ---------------- readout: out = h2_final @ Wfc + b_fc ----------------
__global__ void final_kernel(const float* __restrict__ Wfc,
                             const float* __restrict__ bfc,
                             float* __restrict__ out) {
    int idx = blockIdx.x * blockDim.x + threadIdx.x;
    if (idx >= B_SZ * C_SZ) return;
    int b = idx / C_SZ, c = idx % C_SZ;
    const float* h2 = g_h[0][2];  // after t=511 (odd), last write went to buffer 0
    float s = bfc[c];
    #pragma unroll 8
    for (int n = 0; n < N_SZ; ++n) s += h2[(size_t)b * N_SZ + n] * Wfc[n * C_SZ + c];
    out[idx] = s;
}

// ---------------- launch ----------------
extern "C" void kernel_launch(void* const* d_in, const int* in_sizes, int n_in,
                              void* d_out, int out_size) {
    // Defensive: identify inputs by unique element counts (all 10 are distinct).
    const float* data = nullptr; const float* h0 = nullptr;
    const float* Win = nullptr;  const float* b_in = nullptr;
    const float* Whh = nullptr;  const float* b_hh = nullptr;
    const float* Whi = nullptr;  const float* b_hi = nullptr;
    const float* Wfc = nullptr;  const float* b_fc = nullptr;
    for (int i = 0; i < n_in; ++i) {
        const float* ptr = (const float*)d_in[i];
        switch (in_sizes[i]) {
            case T_STEPS * B_SZ * I_SZ: data = ptr; break;   // 8388608
            case L_SZ * B_SZ * N_SZ:    h0 = ptr; break;     // 393216
            case I_SZ * N_SZ:           Win = ptr; break;    // 32768
            case N_SZ:                  b_in = ptr; break;   // 512
            case 3 * NN:                Whh = ptr; break;    // 786432
            case 3 * N_SZ:              b_hh = ptr; break;   // 1536
            case 2 * NN:                Whi = ptr; break;    // 524288
            case 2 * N_SZ:              b_hi = ptr; break;   // 1024
            case N_SZ * C_SZ:           Wfc = ptr; break;    // 5120
            case C_SZ:                  b_fc = ptr; break;   // 10
            default: break;
        }
    }
    float* out = (float*)d_out;

    prep_kernel<<<(3 * NN + 255) / 256, 256>>>(Whh, b_hh, Whi, b_hi, h0);
    xproj_kernel<<<dim3((T_STEPS * B_SZ) / 64, N_SZ / 32), 256>>>(data, Win, b_in);
    rnn_kernel<<<G_CTAS, 256>>>();
    final_kernel<<<(B_SZ * C_SZ + 255) / 256, 256>>>(Wfc, b_fc, out);
}